// round 10
// baseline (speedup 1.0000x reference)
#include <cuda_runtime.h>
#include <cuda_bf16.h>
#include <cstdint>

// Problem constants (fixed by setup_inputs)
#define Bb 4
#define Tt 2048
#define Cc 768
#define Hh 12
#define DH 64
#define Mm (Bb * Tt)      // 8192
#define N3 (3 * Cc)       // 2304
#define NKSTEP (Cc / 16)  // 48

// ---------------------------------------------------------------------------
// Device scratch: bf16 hi/lo splits.
// x splits TRANSPOSED: [K][M]. W splits natural [K][N]. q/k/v: [B,H,T,D].
// ---------------------------------------------------------------------------
__device__ __nv_bfloat16 g_xh[(size_t)Cc * Mm], g_xl[(size_t)Cc * Mm];
__device__ __nv_bfloat16 g_wh[(size_t)Cc * N3], g_wl[(size_t)Cc * N3];
__device__ __nv_bfloat16 g_qh[(size_t)Bb * Hh * Tt * DH], g_ql[(size_t)Bb * Hh * Tt * DH];
__device__ __nv_bfloat16 g_kh[(size_t)Bb * Hh * Tt * DH], g_kl[(size_t)Bb * Hh * Tt * DH];
__device__ __nv_bfloat16 g_vh[(size_t)Bb * Hh * Tt * DH], g_vl[(size_t)Bb * Hh * Tt * DH];

// ---------------------------------------------------------------------------
// Helpers
// ---------------------------------------------------------------------------
__device__ __forceinline__ uint32_t smem_u32(const void* p) {
    uint32_t a;
    asm("{ .reg .u64 t; cvta.to.shared.u64 t, %1; cvt.u32.u64 %0, t; }"
        : "=r"(a) : "l"(p));
    return a;
}
__device__ __forceinline__ void ldsm4(uint32_t r[4], uint32_t a) {
    asm volatile("ldmatrix.sync.aligned.m8n8.x4.shared.b16 {%0,%1,%2,%3}, [%4];"
                 : "=r"(r[0]), "=r"(r[1]), "=r"(r[2]), "=r"(r[3]) : "r"(a));
}
__device__ __forceinline__ void ldsm4t(uint32_t r[4], uint32_t a) {
    asm volatile("ldmatrix.sync.aligned.m8n8.x4.trans.shared.b16 {%0,%1,%2,%3}, [%4];"
                 : "=r"(r[0]), "=r"(r[1]), "=r"(r[2]), "=r"(r[3]) : "r"(a));
}
__device__ __forceinline__ void mma16816(float* c, const uint32_t* a, uint32_t b0, uint32_t b1) {
    asm volatile(
        "mma.sync.aligned.m16n8k16.row.col.f32.bf16.bf16.f32 "
        "{%0,%1,%2,%3}, {%4,%5,%6,%7}, {%8,%9}, {%0,%1,%2,%3};"
        : "+f"(c[0]), "+f"(c[1]), "+f"(c[2]), "+f"(c[3])
        : "r"(a[0]), "r"(a[1]), "r"(a[2]), "r"(a[3]), "r"(b0), "r"(b1));
}
// Fast bf16x3 split: packed cvt; hi halves recovered by bit ops.
__device__ __forceinline__ void split_pack(float x0, float x1, uint32_t& hi, uint32_t& lo) {
    uint32_t h;
    asm("cvt.rn.bf16x2.f32 %0, %1, %2;" : "=r"(h) : "f"(x1), "f"(x0));
    const float h0 = __uint_as_float(h << 16);
    const float h1 = __uint_as_float(h & 0xFFFF0000u);
    uint32_t lw;
    asm("cvt.rn.bf16x2.f32 %0, %1, %2;" : "=r"(lw) : "f"(x1 - h1), "f"(x0 - h0));
    hi = h; lo = lw;
}

#define CP16(s, g) \
    asm volatile("cp.async.cg.shared.global [%0], [%1], 16;" :: "r"(s), "l"(g))
#define CP_COMMIT() asm volatile("cp.async.commit_group;" ::: "memory")
#define CP_WAIT0()  asm volatile("cp.async.wait_group 0;" ::: "memory")
#define CP_WAIT1()  asm volatile("cp.async.wait_group 1;" ::: "memory")

#define SWZ(row, byteoff) ((byteoff) ^ (((row) & 7) << 4))

// ---------------------------------------------------------------------------
// cvt_x: fp32 x[M][K] -> bf16 hi/lo TRANSPOSED [K][M]
// ---------------------------------------------------------------------------
__global__ __launch_bounds__(256) void cvt_x(const float* __restrict__ x) {
    __shared__ float S[64][65];
    const int m0 = blockIdx.x * 64, k0 = blockIdx.y * 64;
    const int tid = threadIdx.x;
#pragma unroll
    for (int i = 0; i < 4; i++) {
        const int c = tid + i * 256;
        const int row = c >> 4;
        const int c4 = (c & 15) * 4;
        float4 v = *(const float4*)&x[(size_t)(m0 + row) * Cc + k0 + c4];
        S[row][c4] = v.x; S[row][c4 + 1] = v.y; S[row][c4 + 2] = v.z; S[row][c4 + 3] = v.w;
    }
    __syncthreads();
#pragma unroll
    for (int i = 0; i < 2; i++) {
        const int c = tid + i * 256;
        const int k = c >> 3;
        const int mc = c & 7;
        uint32_t hw[4], lw[4];
#pragma unroll
        for (int e = 0; e < 4; e++)
            split_pack(S[mc * 8 + 2 * e][k], S[mc * 8 + 2 * e + 1][k], hw[e], lw[e]);
        const size_t g = (size_t)(k0 + k) * Mm + m0 + mc * 8;
        *(uint4*)&g_xh[g] = make_uint4(hw[0], hw[1], hw[2], hw[3]);
        *(uint4*)&g_xl[g] = make_uint4(lw[0], lw[1], lw[2], lw[3]);
    }
}
__global__ __launch_bounds__(256) void cvt_w(const float* __restrict__ W) {
    const size_t base = ((size_t)blockIdx.x * 256 + threadIdx.x) * 4;
    float4 v = *(const float4*)&W[base];
    uint32_t h01, l01, h23, l23;
    split_pack(v.x, v.y, h01, l01);
    split_pack(v.z, v.w, h23, l23);
    *(uint2*)&g_wh[base] = make_uint2(h01, h23);
    *(uint2*)&g_wl[base] = make_uint2(l01, l23);
}

// ---------------------------------------------------------------------------
// Kernel 1: qkv = x @ W + b via mma.sync bf16x3 (unchanged from R9).
// 128x128 block, 128 thr, 4 warps (2m x 2n), warp 64x64.
// 64KB dynamic smem: 2 super-stages x 32KB (each 2 x 16KB sub-stages).
// ---------------------------------------------------------------------------
__global__ __launch_bounds__(128) void qkv_mma(const float* __restrict__ bias) {
    extern __shared__ __align__(128) uint8_t smd[];
    const uint32_t uS = smem_u32(smd);

    const int tid = threadIdx.x;
    const int l   = tid & 31;
    const int w   = tid >> 5;
    const int wm  = w >> 1;
    const int wn  = w & 1;
    const int m0  = blockIdx.y * 128;
    const int n0  = blockIdx.x * 128;

    float acc[4][8][4];
#pragma unroll
    for (int i = 0; i < 4; i++)
#pragma unroll
        for (int j = 0; j < 8; j++)
#pragma unroll
            for (int r = 0; r < 4; r++) acc[i][j][r] = 0.f;

    const int cr = tid >> 3;
    const int cc = (tid & 7) * 2;
    const uint32_t so0 = (uint32_t)SWZ(cr, cr * 256 + cc * 16);
    const uint32_t so1 = (uint32_t)SWZ(cr, cr * 256 + cc * 16 + 16);

#define QKV_SUB(kb, bofs) do {                                                \
    const int _k = (kb) * 16 + cr;                                            \
    const uint32_t _b = uS + (bofs);                                          \
    const size_t _ga = (size_t)_k * Mm + m0 + cc * 8;                         \
    const size_t _gb = (size_t)_k * N3 + n0 + cc * 8;                         \
    CP16(_b + so0,         g_xh + _ga);                                       \
    CP16(_b + so1,         g_xh + _ga + 8);                                   \
    CP16(_b + 4096 + so0,  g_xl + _ga);                                       \
    CP16(_b + 4096 + so1,  g_xl + _ga + 8);                                   \
    CP16(_b + 8192 + so0,  g_wh + _gb);                                       \
    CP16(_b + 8192 + so1,  g_wh + _gb + 8);                                   \
    CP16(_b + 12288 + so0, g_wl + _gb);                                       \
    CP16(_b + 12288 + so1, g_wl + _gb + 8);                                   \
} while (0)

#define QKV_ISSUE2(kb, sst) do {                                              \
    QKV_SUB(kb, (sst) * 32768);                                               \
    QKV_SUB((kb) + 1, (sst) * 32768 + 16384);                                 \
    CP_COMMIT();                                                              \
} while (0)

    const int arow = (l & 7) + 8 * (l >> 4);
    const int abyt = wm * 128 + ((l >> 3) & 1) * 16;
    const int brow = (l & 15);
    const int bbyt = wn * 128 + (l >> 4) * 16;

    QKV_ISSUE2(0, 0);

    for (int kb2 = 0; kb2 < NKSTEP / 2; kb2++) {       // 24 rounds
        CP_WAIT0();
        __syncthreads();
        if (kb2 + 1 < NKSTEP / 2) QKV_ISSUE2(2 * (kb2 + 1), (kb2 + 1) & 1);

        const uint32_t superb = uS + (kb2 & 1) * 32768;
#pragma unroll
        for (int sub = 0; sub < 2; sub++) {
            const uint32_t sb = superb + sub * 16384;
            uint32_t fa[2][4][4], fb[2][4][4];
#pragma unroll
            for (int sp = 0; sp < 2; sp++) {
#pragma unroll
                for (int mt = 0; mt < 4; mt++)
                    ldsm4t(fa[sp][mt], sb + sp * 4096 + SWZ(arow, arow * 256 + abyt + mt * 32));
#pragma unroll
                for (int g = 0; g < 4; g++)
                    ldsm4t(fb[sp][g], sb + 8192 + sp * 4096 + SWZ(brow, brow * 256 + bbyt + g * 32));
            }

#pragma unroll
            for (int mt = 0; mt < 4; mt++)
#pragma unroll
                for (int nt = 0; nt < 8; nt++) {
                    const int g = nt >> 1, i2 = (nt & 1) * 2;
                    mma16816(acc[mt][nt], fa[0][mt], fb[0][g][i2], fb[0][g][i2 + 1]);
                    mma16816(acc[mt][nt], fa[0][mt], fb[1][g][i2], fb[1][g][i2 + 1]);
                    mma16816(acc[mt][nt], fa[1][mt], fb[0][g][i2], fb[0][g][i2 + 1]);
                }
        }
    }

    // ---- Epilogue ----
    const int which = n0 / Cc;
    const int nloc0 = n0 - which * Cc;
    const float scale = (which == 0) ? 0.125f : 1.0f;
    __nv_bfloat16* dh = (which == 0) ? g_qh : (which == 1) ? g_kh : g_vh;
    __nv_bfloat16* dl = (which == 0) ? g_ql : (which == 1) ? g_kl : g_vl;

    const int mrow = m0 + wm * 64 + (l >> 2);
    const int b_   = mrow >> 11;
#pragma unroll
    for (int mt = 0; mt < 4; mt++) {
        const int t1 = (mrow + mt * 16) & (Tt - 1);
#pragma unroll
        for (int nt = 0; nt < 8; nt++) {
            const int n  = nloc0 + wn * 64 + nt * 8 + 2 * (l & 3);
            const int hh = n >> 6;
            const int d  = n & 63;
            const float b0 = bias[which * Cc + n];
            const float b1 = bias[which * Cc + n + 1];
            uint32_t h01, l01, h23, l23;
            split_pack((acc[mt][nt][0] + b0) * scale, (acc[mt][nt][1] + b1) * scale, h01, l01);
            split_pack((acc[mt][nt][2] + b0) * scale, (acc[mt][nt][3] + b1) * scale, h23, l23);
            const size_t i1 = (((size_t)b_ * Hh + hh) * Tt + t1) * DH + d;
            const size_t i2 = i1 + (size_t)8 * DH;
            *(uint32_t*)&dh[i1] = h01;  *(uint32_t*)&dl[i1] = l01;
            *(uint32_t*)&dh[i2] = h23;  *(uint32_t*)&dl[i2] = l23;
        }
    }
}

// ---------------------------------------------------------------------------
// Kernel 2: causal ReLU attention, BQ=64, BK=32, bf16x3.
// Static 48KB: 3-stage ring x 16KB (K_hi +0, K_lo +4096, V_hi +8192,
// V_lo +12288), depth 2. Q fragments via direct LDG. Forced 4 blocks/SM.
// ---------------------------------------------------------------------------
__global__ __launch_bounds__(128, 4) void attn_mma(float* __restrict__ out)
{
    __shared__ __align__(128) uint8_t sm[49152];
    const uint32_t uS = smem_u32(sm);

    const int tid = threadIdx.x;
    const int l   = tid & 31;
    const int w   = tid >> 5;
    const int qt  = (gridDim.x - 1) - blockIdx.x;    // 0..31, long first
    const int h   = blockIdx.y;
    const int b   = blockIdx.z;

    const size_t hb = ((size_t)b * Hh + h) * (size_t)Tt * DH;

#define ATT_ISSUE(j2, st) do {                                              \
    const uint32_t _sb = uS + (st) * 16384;                                 \
    _Pragma("unroll")                                                       \
    for (int _i = 0; _i < 2; _i++) {                                        \
        const int _c = tid + _i * 128;       /* 0..255 */                   \
        const int _row = _c >> 3;            /* 0..31  */                   \
        const int _c16 = _c & 7;                                            \
        const uint32_t _so = SWZ(_row, _row * 128 + _c16 * 16);             \
        const size_t _g = hb + (size_t)((j2) * 32 + _row) * DH + _c16 * 8;  \
        CP16(_sb + _so,         g_kh + _g);                                 \
        CP16(_sb + 4096 + _so,  g_kl + _g);                                 \
        CP16(_sb + 8192 + _so,  g_vh + _g);                                 \
        CP16(_sb + 12288 + _so, g_vl + _g);                                 \
    }                                                                       \
    CP_COMMIT();                                                            \
} while (0)

    const int ntile = 2 * (qt + 1);      // >= 2

    ATT_ISSUE(0, 0);
    ATT_ISSUE(1, 1);

    // Q fragments via direct LDG (matches mma A-fragment layout exactly)
    uint32_t fq[2][4][4];
    const int r0 = qt * 64 + w * 16 + (l >> 2);
    {
        const size_t qb0 = hb + (size_t)r0 * DH;
        const size_t qb1 = qb0 + (size_t)8 * DH;
#pragma unroll
        for (int ks = 0; ks < 4; ks++) {
            const int c0 = ks * 16 + (l & 3) * 2;
            fq[0][ks][0] = *(const uint32_t*)&g_qh[qb0 + c0];
            fq[0][ks][1] = *(const uint32_t*)&g_qh[qb1 + c0];
            fq[0][ks][2] = *(const uint32_t*)&g_qh[qb0 + c0 + 8];
            fq[0][ks][3] = *(const uint32_t*)&g_qh[qb1 + c0 + 8];
            fq[1][ks][0] = *(const uint32_t*)&g_ql[qb0 + c0];
            fq[1][ks][1] = *(const uint32_t*)&g_ql[qb1 + c0];
            fq[1][ks][2] = *(const uint32_t*)&g_ql[qb0 + c0 + 8];
            fq[1][ks][3] = *(const uint32_t*)&g_ql[qb1 + c0 + 8];
        }
    }

    float o[8][4];
#pragma unroll
    for (int i = 0; i < 8; i++)
#pragma unroll
        for (int r = 0; r < 4; r++) o[i][r] = 0.f;

    const int rowg = r0;
    int st = 0;

    for (int j2 = 0; j2 < ntile; j2++) {
        if (j2 == ntile - 1) CP_WAIT0(); else CP_WAIT1();
        __syncthreads();
        if (j2 + 2 < ntile) ATT_ISSUE(j2 + 2, (st + 2 > 2) ? st - 1 : st + 2);

        const uint32_t sb = uS + st * 16384;

        // ---- S = Q . K^T (64 q x 32 k) ----
        float s[4][4];
#pragma unroll
        for (int i = 0; i < 4; i++)
#pragma unroll
            for (int r = 0; r < 4; r++) s[i][r] = 0.f;

        const int nrow = (l & 7) + 8 * (l >> 4);
#pragma unroll
        for (int ks = 0; ks < 4; ks++) {
            uint32_t fk[2][2][4];
            const int cb = (ks * 16 + 8 * ((l >> 3) & 1)) * 2;
#pragma unroll
            for (int sp = 0; sp < 2; sp++)
#pragma unroll
                for (int g = 0; g < 2; g++) {
                    const int rr = g * 16 + nrow;
                    ldsm4(fk[sp][g], sb + sp * 4096 + SWZ(rr, rr * 128 + cb));
                }
#pragma unroll
            for (int nt = 0; nt < 4; nt++) {
                const int g = nt >> 1, i2 = (nt & 1) * 2;
                mma16816(s[nt], fq[0][ks], fk[0][g][i2], fk[0][g][i2 + 1]);
                mma16816(s[nt], fq[0][ks], fk[1][g][i2], fk[1][g][i2 + 1]);
                mma16816(s[nt], fq[1][ks], fk[0][g][i2], fk[0][g][i2 + 1]);
            }
        }

        // ---- ReLU + causal mask + split into P fragments ----
        uint32_t ph[2][4], pl[2][4];
        const bool nm = (j2 * 32 + 31 > qt * 64 + w * 16);
#pragma unroll
        for (int nt = 0; nt < 4; nt++) {
            const int colg = j2 * 32 + nt * 8 + 2 * (l & 3);
            float v0 = fmaxf(s[nt][0], 0.f);
            float v1 = fmaxf(s[nt][1], 0.f);
            float v2 = fmaxf(s[nt][2], 0.f);
            float v3 = fmaxf(s[nt][3], 0.f);
            if (nm) {
                if (colg     > rowg)     v0 = 0.f;
                if (colg + 1 > rowg)     v1 = 0.f;
                if (colg     > rowg + 8) v2 = 0.f;
                if (colg + 1 > rowg + 8) v3 = 0.f;
            }
            const int js = nt >> 1, pos = (nt & 1) * 2;
            split_pack(v0, v1, ph[js][pos],     pl[js][pos]);
            split_pack(v2, v3, ph[js][pos + 1], pl[js][pos + 1]);
        }

        // ---- O += P . V (k=32) ----
#pragma unroll
        for (int js = 0; js < 2; js++) {
            uint32_t fv[2][4][4];
            const int vrow = js * 16 + (l & 15);
#pragma unroll
            for (int sp = 0; sp < 2; sp++)
#pragma unroll
                for (int g = 0; g < 4; g++) {
                    const int cb = (g * 16 + (l >> 4) * 8) * 2;
                    ldsm4t(fv[sp][g], sb + 8192 + sp * 4096 + SWZ(vrow, vrow * 128 + cb));
                }
#pragma unroll
            for (int dt = 0; dt < 8; dt++) {
                const int g = dt >> 1, i2 = (dt & 1) * 2;
                mma16816(o[dt], ph[js], fv[0][g][i2], fv[0][g][i2 + 1]);
                mma16816(o[dt], ph[js], fv[1][g][i2], fv[1][g][i2 + 1]);
                mma16816(o[dt], pl[js], fv[0][g][i2], fv[0][g][i2 + 1]);
            }
        }

        st = (st == 2) ? 0 : st + 1;
    }

    // ---- store O ----
#pragma unroll
    for (int dt = 0; dt < 8; dt++) {
        const int col = h * DH + dt * 8 + 2 * (l & 3);
        *(float2*)&out[((size_t)b * Tt + rowg) * Cc + col]     = make_float2(o[dt][0], o[dt][1]);
        *(float2*)&out[((size_t)b * Tt + rowg + 8) * Cc + col] = make_float2(o[dt][2], o[dt][3]);
    }
}

// ---------------------------------------------------------------------------
extern "C" void kernel_launch(void* const* d_in, const int* in_sizes, int n_in,
                              void* d_out, int out_size)
{
    const float* x    = (const float*)d_in[0];
    const float* W    = (const float*)d_in[1];
    const float* bias = (const float*)d_in[2];
    float* out        = (float*)d_out;
    (void)in_sizes; (void)n_in; (void)out_size;

    // Unlock 64KB dynamic smem for qkv (idempotent; not a stream operation).
    cudaFuncSetAttribute(qkv_mma, cudaFuncAttributeMaxDynamicSharedMemorySize, 65536);

    cvt_x<<<dim3(Mm / 64, Cc / 64), 256>>>(x);
    cvt_w<<<(Cc * N3) / 1024, 256>>>(W);

    dim3 g1(N3 / 128, Mm / 128);    // (18, 64)
    qkv_mma<<<g1, 128, 65536>>>(bias);

    dim3 g2(Tt / 64, Hh, Bb);       // (32, 12, 4)
    attn_mma<<<g2, 128>>>(out);
}

// round 11
// speedup vs baseline: 1.0199x; 1.0199x over previous
#include <cuda_runtime.h>
#include <cuda_bf16.h>
#include <cstdint>

// Problem constants (fixed by setup_inputs)
#define Bb 4
#define Tt 2048
#define Cc 768
#define Hh 12
#define DH 64
#define Mm (Bb * Tt)      // 8192
#define N3 (3 * Cc)       // 2304
#define NKSTEP (Cc / 16)  // 48

// ---------------------------------------------------------------------------
// Device scratch: bf16 hi/lo splits.
// x splits TRANSPOSED: [K][M]. W splits natural [K][N]. q/k/v: [B,H,T,D].
// ---------------------------------------------------------------------------
__device__ __nv_bfloat16 g_xh[(size_t)Cc * Mm], g_xl[(size_t)Cc * Mm];
__device__ __nv_bfloat16 g_wh[(size_t)Cc * N3], g_wl[(size_t)Cc * N3];
__device__ __nv_bfloat16 g_qh[(size_t)Bb * Hh * Tt * DH], g_ql[(size_t)Bb * Hh * Tt * DH];
__device__ __nv_bfloat16 g_kh[(size_t)Bb * Hh * Tt * DH], g_kl[(size_t)Bb * Hh * Tt * DH];
__device__ __nv_bfloat16 g_vh[(size_t)Bb * Hh * Tt * DH], g_vl[(size_t)Bb * Hh * Tt * DH];

// ---------------------------------------------------------------------------
// Helpers
// ---------------------------------------------------------------------------
__device__ __forceinline__ uint32_t smem_u32(const void* p) {
    uint32_t a;
    asm("{ .reg .u64 t; cvta.to.shared.u64 t, %1; cvt.u32.u64 %0, t; }"
        : "=r"(a) : "l"(p));
    return a;
}
__device__ __forceinline__ void ldsm4(uint32_t r[4], uint32_t a) {
    asm volatile("ldmatrix.sync.aligned.m8n8.x4.shared.b16 {%0,%1,%2,%3}, [%4];"
                 : "=r"(r[0]), "=r"(r[1]), "=r"(r[2]), "=r"(r[3]) : "r"(a));
}
__device__ __forceinline__ void ldsm4t(uint32_t r[4], uint32_t a) {
    asm volatile("ldmatrix.sync.aligned.m8n8.x4.trans.shared.b16 {%0,%1,%2,%3}, [%4];"
                 : "=r"(r[0]), "=r"(r[1]), "=r"(r[2]), "=r"(r[3]) : "r"(a));
}
__device__ __forceinline__ void mma16816(float* c, const uint32_t* a, uint32_t b0, uint32_t b1) {
    asm volatile(
        "mma.sync.aligned.m16n8k16.row.col.f32.bf16.bf16.f32 "
        "{%0,%1,%2,%3}, {%4,%5,%6,%7}, {%8,%9}, {%0,%1,%2,%3};"
        : "+f"(c[0]), "+f"(c[1]), "+f"(c[2]), "+f"(c[3])
        : "r"(a[0]), "r"(a[1]), "r"(a[2]), "r"(a[3]), "r"(b0), "r"(b1));
}
// Fast bf16x3 split: packed cvt; hi halves recovered by bit ops.
__device__ __forceinline__ void split_pack(float x0, float x1, uint32_t& hi, uint32_t& lo) {
    uint32_t h;
    asm("cvt.rn.bf16x2.f32 %0, %1, %2;" : "=r"(h) : "f"(x1), "f"(x0));
    const float h0 = __uint_as_float(h << 16);
    const float h1 = __uint_as_float(h & 0xFFFF0000u);
    uint32_t lw;
    asm("cvt.rn.bf16x2.f32 %0, %1, %2;" : "=r"(lw) : "f"(x1 - h1), "f"(x0 - h0));
    hi = h; lo = lw;
}

#define CP16(s, g) \
    asm volatile("cp.async.cg.shared.global [%0], [%1], 16;" :: "r"(s), "l"(g))
#define CP_COMMIT() asm volatile("cp.async.commit_group;" ::: "memory")
#define CP_WAIT0()  asm volatile("cp.async.wait_group 0;" ::: "memory")

#define SWZ(row, byteoff) ((byteoff) ^ (((row) & 7) << 4))

// ---------------------------------------------------------------------------
// cvt_x: fp32 x[M][K] -> bf16 hi/lo TRANSPOSED [K][M]
// ---------------------------------------------------------------------------
__global__ __launch_bounds__(256) void cvt_x(const float* __restrict__ x) {
    __shared__ float S[64][65];
    const int m0 = blockIdx.x * 64, k0 = blockIdx.y * 64;
    const int tid = threadIdx.x;
#pragma unroll
    for (int i = 0; i < 4; i++) {
        const int c = tid + i * 256;
        const int row = c >> 4;
        const int c4 = (c & 15) * 4;
        float4 v = *(const float4*)&x[(size_t)(m0 + row) * Cc + k0 + c4];
        S[row][c4] = v.x; S[row][c4 + 1] = v.y; S[row][c4 + 2] = v.z; S[row][c4 + 3] = v.w;
    }
    __syncthreads();
#pragma unroll
    for (int i = 0; i < 2; i++) {
        const int c = tid + i * 256;
        const int k = c >> 3;
        const int mc = c & 7;
        uint32_t hw[4], lw[4];
#pragma unroll
        for (int e = 0; e < 4; e++)
            split_pack(S[mc * 8 + 2 * e][k], S[mc * 8 + 2 * e + 1][k], hw[e], lw[e]);
        const size_t g = (size_t)(k0 + k) * Mm + m0 + mc * 8;
        *(uint4*)&g_xh[g] = make_uint4(hw[0], hw[1], hw[2], hw[3]);
        *(uint4*)&g_xl[g] = make_uint4(lw[0], lw[1], lw[2], lw[3]);
    }
}
__global__ __launch_bounds__(256) void cvt_w(const float* __restrict__ W) {
    const size_t base = ((size_t)blockIdx.x * 256 + threadIdx.x) * 4;
    float4 v = *(const float4*)&W[base];
    uint32_t h01, l01, h23, l23;
    split_pack(v.x, v.y, h01, l01);
    split_pack(v.z, v.w, h23, l23);
    *(uint2*)&g_wh[base] = make_uint2(h01, h23);
    *(uint2*)&g_wl[base] = make_uint2(l01, l23);
}

// ---------------------------------------------------------------------------
// Kernel 1: qkv = x @ W + b via mma.sync bf16x3 (unchanged from R9).
// 128x128 block, 128 thr, 4 warps (2m x 2n), warp 64x64.
// 64KB dynamic smem: 2 super-stages x 32KB (each 2 x 16KB sub-stages).
// ---------------------------------------------------------------------------
__global__ __launch_bounds__(128) void qkv_mma(const float* __restrict__ bias) {
    extern __shared__ __align__(128) uint8_t smd[];
    const uint32_t uS = smem_u32(smd);

    const int tid = threadIdx.x;
    const int l   = tid & 31;
    const int w   = tid >> 5;
    const int wm  = w >> 1;
    const int wn  = w & 1;
    const int m0  = blockIdx.y * 128;
    const int n0  = blockIdx.x * 128;

    float acc[4][8][4];
#pragma unroll
    for (int i = 0; i < 4; i++)
#pragma unroll
        for (int j = 0; j < 8; j++)
#pragma unroll
            for (int r = 0; r < 4; r++) acc[i][j][r] = 0.f;

    const int cr = tid >> 3;
    const int cc = (tid & 7) * 2;
    const uint32_t so0 = (uint32_t)SWZ(cr, cr * 256 + cc * 16);
    const uint32_t so1 = (uint32_t)SWZ(cr, cr * 256 + cc * 16 + 16);

#define QKV_SUB(kb, bofs) do {                                                \
    const int _k = (kb) * 16 + cr;                                            \
    const uint32_t _b = uS + (bofs);                                          \
    const size_t _ga = (size_t)_k * Mm + m0 + cc * 8;                         \
    const size_t _gb = (size_t)_k * N3 + n0 + cc * 8;                         \
    CP16(_b + so0,         g_xh + _ga);                                       \
    CP16(_b + so1,         g_xh + _ga + 8);                                   \
    CP16(_b + 4096 + so0,  g_xl + _ga);                                       \
    CP16(_b + 4096 + so1,  g_xl + _ga + 8);                                   \
    CP16(_b + 8192 + so0,  g_wh + _gb);                                       \
    CP16(_b + 8192 + so1,  g_wh + _gb + 8);                                   \
    CP16(_b + 12288 + so0, g_wl + _gb);                                       \
    CP16(_b + 12288 + so1, g_wl + _gb + 8);                                   \
} while (0)

#define QKV_ISSUE2(kb, sst) do {                                              \
    QKV_SUB(kb, (sst) * 32768);                                               \
    QKV_SUB((kb) + 1, (sst) * 32768 + 16384);                                 \
    CP_COMMIT();                                                              \
} while (0)

    const int arow = (l & 7) + 8 * (l >> 4);
    const int abyt = wm * 128 + ((l >> 3) & 1) * 16;
    const int brow = (l & 15);
    const int bbyt = wn * 128 + (l >> 4) * 16;

    QKV_ISSUE2(0, 0);

    for (int kb2 = 0; kb2 < NKSTEP / 2; kb2++) {       // 24 rounds
        CP_WAIT0();
        __syncthreads();
        if (kb2 + 1 < NKSTEP / 2) QKV_ISSUE2(2 * (kb2 + 1), (kb2 + 1) & 1);

        const uint32_t superb = uS + (kb2 & 1) * 32768;
#pragma unroll
        for (int sub = 0; sub < 2; sub++) {
            const uint32_t sb = superb + sub * 16384;
            uint32_t fa[2][4][4], fb[2][4][4];
#pragma unroll
            for (int sp = 0; sp < 2; sp++) {
#pragma unroll
                for (int mt = 0; mt < 4; mt++)
                    ldsm4t(fa[sp][mt], sb + sp * 4096 + SWZ(arow, arow * 256 + abyt + mt * 32));
#pragma unroll
                for (int g = 0; g < 4; g++)
                    ldsm4t(fb[sp][g], sb + 8192 + sp * 4096 + SWZ(brow, brow * 256 + bbyt + g * 32));
            }

#pragma unroll
            for (int mt = 0; mt < 4; mt++)
#pragma unroll
                for (int nt = 0; nt < 8; nt++) {
                    const int g = nt >> 1, i2 = (nt & 1) * 2;
                    mma16816(acc[mt][nt], fa[0][mt], fb[0][g][i2], fb[0][g][i2 + 1]);
                    mma16816(acc[mt][nt], fa[0][mt], fb[1][g][i2], fb[1][g][i2 + 1]);
                    mma16816(acc[mt][nt], fa[1][mt], fb[0][g][i2], fb[0][g][i2 + 1]);
                }
        }
    }

    // ---- Epilogue ----
    const int which = n0 / Cc;
    const int nloc0 = n0 - which * Cc;
    const float scale = (which == 0) ? 0.125f : 1.0f;
    __nv_bfloat16* dh = (which == 0) ? g_qh : (which == 1) ? g_kh : g_vh;
    __nv_bfloat16* dl = (which == 0) ? g_ql : (which == 1) ? g_kl : g_vl;

    const int mrow = m0 + wm * 64 + (l >> 2);
    const int b_   = mrow >> 11;
#pragma unroll
    for (int mt = 0; mt < 4; mt++) {
        const int t1 = (mrow + mt * 16) & (Tt - 1);
#pragma unroll
        for (int nt = 0; nt < 8; nt++) {
            const int n  = nloc0 + wn * 64 + nt * 8 + 2 * (l & 3);
            const int hh = n >> 6;
            const int d  = n & 63;
            const float b0 = bias[which * Cc + n];
            const float b1 = bias[which * Cc + n + 1];
            uint32_t h01, l01, h23, l23;
            split_pack((acc[mt][nt][0] + b0) * scale, (acc[mt][nt][1] + b1) * scale, h01, l01);
            split_pack((acc[mt][nt][2] + b0) * scale, (acc[mt][nt][3] + b1) * scale, h23, l23);
            const size_t i1 = (((size_t)b_ * Hh + hh) * Tt + t1) * DH + d;
            const size_t i2 = i1 + (size_t)8 * DH;
            *(uint32_t*)&dh[i1] = h01;  *(uint32_t*)&dl[i1] = l01;
            *(uint32_t*)&dh[i2] = h23;  *(uint32_t*)&dl[i2] = l23;
        }
    }
}

// ---------------------------------------------------------------------------
// Kernel 2: causal ReLU attention, BQ=64, BK=64 per sync round, bf16x3.
// 64KB dynamic smem: 2 super-stages x 32KB (each 2 x 16KB sub-tiles:
// K_hi +0, K_lo +4096, V_hi +8192, V_lo +12288). Q fragments via direct LDG.
// Phase-interleaved schedule: S(0);S(1); split(0);PV(0); split(1);PV(1)
// so split/mask ALU issues while the tensor pipe drains queued mma.
// ---------------------------------------------------------------------------
__global__ __launch_bounds__(128) void attn_mma(float* __restrict__ out)
{
    extern __shared__ __align__(128) uint8_t smd[];
    const uint32_t uS = smem_u32(smd);

    const int tid = threadIdx.x;
    const int l   = tid & 31;
    const int w   = tid >> 5;
    const int qt  = (gridDim.x - 1) - blockIdx.x;    // 0..31, long first
    const int h   = blockIdx.y;
    const int b   = blockIdx.z;

    const size_t hb = ((size_t)b * Hh + h) * (size_t)Tt * DH;

#define ATT_ISSUE2(j64, sst) do {                                           \
    const uint32_t _sb = uS + (sst) * 32768;                                \
    _Pragma("unroll")                                                       \
    for (int _i = 0; _i < 4; _i++) {                                        \
        const int _c = tid + _i * 128;       /* 0..511 */                   \
        const int _row = _c >> 3;            /* 0..63  */                   \
        const int _c16 = _c & 7;                                            \
        const int _sr  = _row & 31;                                         \
        const uint32_t _so = ((_row & 32) ? 16384u : 0u)                    \
                           + SWZ(_sr, _sr * 128 + _c16 * 16);               \
        const size_t _g = hb + (size_t)((j64) * 64 + _row) * DH + _c16 * 8; \
        CP16(_sb + _so,         g_kh + _g);                                 \
        CP16(_sb + 4096 + _so,  g_kl + _g);                                 \
        CP16(_sb + 8192 + _so,  g_vh + _g);                                 \
        CP16(_sb + 12288 + _so, g_vl + _g);                                 \
    }                                                                       \
    CP_COMMIT();                                                            \
} while (0)

    ATT_ISSUE2(0, 0);                 // first 64 kv rows -> super-stage 0

    // Q fragments via direct LDG (matches mma A-fragment layout exactly)
    uint32_t fq[2][4][4];
    const int r0 = qt * 64 + w * 16 + (l >> 2);
    {
        const size_t qb0 = hb + (size_t)r0 * DH;
        const size_t qb1 = qb0 + (size_t)8 * DH;
#pragma unroll
        for (int ks = 0; ks < 4; ks++) {
            const int c0 = ks * 16 + (l & 3) * 2;
            fq[0][ks][0] = *(const uint32_t*)&g_qh[qb0 + c0];
            fq[0][ks][1] = *(const uint32_t*)&g_qh[qb1 + c0];
            fq[0][ks][2] = *(const uint32_t*)&g_qh[qb0 + c0 + 8];
            fq[0][ks][3] = *(const uint32_t*)&g_qh[qb1 + c0 + 8];
            fq[1][ks][0] = *(const uint32_t*)&g_ql[qb0 + c0];
            fq[1][ks][1] = *(const uint32_t*)&g_ql[qb1 + c0];
            fq[1][ks][2] = *(const uint32_t*)&g_ql[qb0 + c0 + 8];
            fq[1][ks][3] = *(const uint32_t*)&g_ql[qb1 + c0 + 8];
        }
    }

    float o[8][4];
#pragma unroll
    for (int i = 0; i < 8; i++)
#pragma unroll
        for (int r = 0; r < 4; r++) o[i][r] = 0.f;

    const int rowg = r0;

    for (int jo = 0; jo <= qt; jo++) {
        CP_WAIT0();
        __syncthreads();
        if (jo < qt) ATT_ISSUE2(jo + 1, (jo + 1) & 1);

        const uint32_t superb = uS + (jo & 1) * 32768;

        // ===== Phase A: S for BOTH sub-tiles (tensor queue stays full) =====
        float s[2][4][4];
#pragma unroll
        for (int sub = 0; sub < 2; sub++)
#pragma unroll
            for (int i = 0; i < 4; i++)
#pragma unroll
                for (int r = 0; r < 4; r++) s[sub][i][r] = 0.f;

        const int nrow = (l & 7) + 8 * (l >> 4);
#pragma unroll
        for (int sub = 0; sub < 2; sub++) {
            const uint32_t sb = superb + sub * 16384;
#pragma unroll
            for (int ks = 0; ks < 4; ks++) {
                uint32_t fk[2][2][4];
                const int cb = (ks * 16 + 8 * ((l >> 3) & 1)) * 2;
#pragma unroll
                for (int sp = 0; sp < 2; sp++)
#pragma unroll
                    for (int g = 0; g < 2; g++) {
                        const int rr = g * 16 + nrow;
                        ldsm4(fk[sp][g], sb + sp * 4096 + SWZ(rr, rr * 128 + cb));
                    }
#pragma unroll
                for (int nt = 0; nt < 4; nt++) {
                    const int g = nt >> 1, i2 = (nt & 1) * 2;
                    mma16816(s[sub][nt], fq[0][ks], fk[0][g][i2], fk[0][g][i2 + 1]);
                    mma16816(s[sub][nt], fq[0][ks], fk[1][g][i2], fk[1][g][i2 + 1]);
                    mma16816(s[sub][nt], fq[1][ks], fk[0][g][i2], fk[0][g][i2 + 1]);
                }
            }
        }

        // ===== Phase B: split + PV per sub-tile; splits overlap tensor drain
#pragma unroll
        for (int sub = 0; sub < 2; sub++) {
            const int j2 = 2 * jo + sub;
            const uint32_t sb = superb + sub * 16384;

            uint32_t ph[2][4], pl[2][4];
            const bool nm = (j2 * 32 + 31 > qt * 64 + w * 16);
#pragma unroll
            for (int nt = 0; nt < 4; nt++) {
                const int colg = j2 * 32 + nt * 8 + 2 * (l & 3);
                float v0 = fmaxf(s[sub][nt][0], 0.f);
                float v1 = fmaxf(s[sub][nt][1], 0.f);
                float v2 = fmaxf(s[sub][nt][2], 0.f);
                float v3 = fmaxf(s[sub][nt][3], 0.f);
                if (nm) {
                    if (colg     > rowg)     v0 = 0.f;
                    if (colg + 1 > rowg)     v1 = 0.f;
                    if (colg     > rowg + 8) v2 = 0.f;
                    if (colg + 1 > rowg + 8) v3 = 0.f;
                }
                const int js = nt >> 1, pos = (nt & 1) * 2;
                split_pack(v0, v1, ph[js][pos],     pl[js][pos]);
                split_pack(v2, v3, ph[js][pos + 1], pl[js][pos + 1]);
            }

#pragma unroll
            for (int js = 0; js < 2; js++) {
                uint32_t fv[2][4][4];
                const int vrow = js * 16 + (l & 15);
#pragma unroll
                for (int sp = 0; sp < 2; sp++)
#pragma unroll
                    for (int g = 0; g < 4; g++) {
                        const int cb = (g * 16 + (l >> 4) * 8) * 2;
                        ldsm4t(fv[sp][g], sb + 8192 + sp * 4096 + SWZ(vrow, vrow * 128 + cb));
                    }
#pragma unroll
                for (int dt = 0; dt < 8; dt++) {
                    const int g = dt >> 1, i2 = (dt & 1) * 2;
                    mma16816(o[dt], ph[js], fv[0][g][i2], fv[0][g][i2 + 1]);
                    mma16816(o[dt], ph[js], fv[1][g][i2], fv[1][g][i2 + 1]);
                    mma16816(o[dt], pl[js], fv[0][g][i2], fv[0][g][i2 + 1]);
                }
            }
        }
    }

    // ---- store O ----
#pragma unroll
    for (int dt = 0; dt < 8; dt++) {
        const int col = h * DH + dt * 8 + 2 * (l & 3);
        *(float2*)&out[((size_t)b * Tt + rowg) * Cc + col]     = make_float2(o[dt][0], o[dt][1]);
        *(float2*)&out[((size_t)b * Tt + rowg + 8) * Cc + col] = make_float2(o[dt][2], o[dt][3]);
    }
}

// ---------------------------------------------------------------------------
extern "C" void kernel_launch(void* const* d_in, const int* in_sizes, int n_in,
                              void* d_out, int out_size)
{
    const float* x    = (const float*)d_in[0];
    const float* W    = (const float*)d_in[1];
    const float* bias = (const float*)d_in[2];
    float* out        = (float*)d_out;
    (void)in_sizes; (void)n_in; (void)out_size;

    // Unlock 64KB dynamic smem (idempotent; not a stream operation).
    cudaFuncSetAttribute(qkv_mma,  cudaFuncAttributeMaxDynamicSharedMemorySize, 65536);
    cudaFuncSetAttribute(attn_mma, cudaFuncAttributeMaxDynamicSharedMemorySize, 65536);

    cvt_x<<<dim3(Mm / 64, Cc / 64), 256>>>(x);
    cvt_w<<<(Cc * N3) / 1024, 256>>>(W);

    dim3 g1(N3 / 128, Mm / 128);    // (18, 64)
    qkv_mma<<<g1, 128, 65536>>>(bias);

    dim3 g2(Tt / 64, Hh, Bb);       // (32, 12, 4)
    attn_mma<<<g2, 128, 65536>>>(out);
}